// round 4
// baseline (speedup 1.0000x reference)
#include <cuda_runtime.h>
#include <math_constants.h>

#define BB 512
#define SS 200
#define UU 50
#define DD 32
#define NITER 13              // ceil(50 rows / 4 rows-per-iter)
#define ROWS_PAD 52           // pad so tail LDS (u=50,51) stays in this warp's tile
#define NEG_INF_V (-1e9f)

__global__ __launch_bounds__(128, 8)
void DIB_attn_kernel(const float* __restrict__ cur_user,   // [B, D]
                     const float* __restrict__ sim_user,   // [B, S, U, D]
                     const float* __restrict__ cur_item,   // [B, S, D]
                     const int* __restrict__ mask,          // [B, S, U] (bool -> int32)
                     float* __restrict__ out)               // [B, S, D]
{
    __shared__ float tile[4][ROWS_PAD * DD];   // 4 warps * 6656B = 26624B/block

    const unsigned FULL = 0xffffffffu;
    int w    = threadIdx.x >> 5;
    int lane = threadIdx.x & 31;
    int gwarp = blockIdx.x * 4 + w;            // grid sized exactly: no bounds check
    int sub  = lane >> 3;                      // 0..3 : row within 4-row group
    int quad = lane & 7;                       // 0..7 : dims quad*4 .. quad*4+3

    int b = gwarp / SS;
    float* tw = tile[w];
    const float* gt = sim_user + (long long)gwarp * (UU * DD);

    // ---- Stage tile into smem with cp.async (no register payload, deep MLP) ----
    #pragma unroll
    for (int i = 0; i < NITER; i++) {
        int u = i * 4 + sub;
        if (u < UU) {
            unsigned saddr = (unsigned)__cvta_generic_to_shared(tw + u * DD + quad * 4);
            const float* gaddr = gt + u * DD + quad * 4;
            asm volatile("cp.async.cg.shared.global [%0], [%1], 16;\n"
                         :: "r"(saddr), "l"(gaddr));
        }
    }
    asm volatile("cp.async.commit_group;\n" ::: "memory");

    // ---- Overlap: load everything else while the tile streams in ----
    float4 cu = __ldg((const float4*)(cur_user + b * DD) + quad);

    const int* mrow = mask + (long long)gwarp * UU;
    int mreg[NITER];
    #pragma unroll
    for (int i = 0; i < NITER; i++) {
        int u = i * 4 + sub;
        mreg[i] = (u < UU) ? __ldg(mrow + u) : 1;
    }

    float4 ci = make_float4(0.f, 0.f, 0.f, 0.f);
    if (sub == 0)
        ci = __ldg((const float4*)(cur_item + (long long)gwarp * DD) + quad);

    asm volatile("cp.async.wait_group 0;\n" ::: "memory");
    __syncwarp();

    // ---- Pass 1: dot products + mask ----
    float sc[NITER];
    #pragma unroll
    for (int i = 0; i < NITER; i++) {
        int u = i * 4 + sub;
        float4 vv = *(const float4*)(tw + u * DD + quad * 4);
        float p = vv.x * cu.x + vv.y * cu.y + vv.z * cu.z + vv.w * cu.w;
        p += __shfl_xor_sync(FULL, p, 1);
        p += __shfl_xor_sync(FULL, p, 2);
        p += __shfl_xor_sync(FULL, p, 4);      // 8-lane group now holds score[u]
        sc[i] = (u < UU) ? (mreg[i] ? NEG_INF_V : p) : -CUDART_INF_F;
    }

    // ---- Softmax over 50 rows (rows distributed across sub groups) ----
    float mx = sc[0];
    #pragma unroll
    for (int i = 1; i < NITER; i++) mx = fmaxf(mx, sc[i]);
    mx = fmaxf(mx, __shfl_xor_sync(FULL, mx, 8));
    mx = fmaxf(mx, __shfl_xor_sync(FULL, mx, 16));

    float e[NITER];
    float s = 0.f;
    #pragma unroll
    for (int i = 0; i < NITER; i++) { e[i] = __expf(sc[i] - mx); s += e[i]; }
    s += __shfl_xor_sync(FULL, s, 8);
    s += __shfl_xor_sync(FULL, s, 16);
    float inv = __frcp_rn(s);

    // ---- Pass 2: weighted sum (weights lane-local, re-read tile from smem) ----
    float4 o = make_float4(0.f, 0.f, 0.f, 0.f);
    #pragma unroll
    for (int i = 0; i < NITER; i++) {
        int u = i * 4 + sub;
        if (u < UU) {                          // guard: tail smem rows are garbage
            float4 vv = *(const float4*)(tw + u * DD + quad * 4);
            float a = e[i] * inv;
            o.x = fmaf(a, vv.x, o.x);
            o.y = fmaf(a, vv.y, o.y);
            o.z = fmaf(a, vv.z, o.z);
            o.w = fmaf(a, vv.w, o.w);
        }
    }

    // Reduce partial outputs across the 4 sub groups.
    #pragma unroll
    for (int off = 8; off <= 16; off <<= 1) {
        o.x += __shfl_xor_sync(FULL, o.x, off);
        o.y += __shfl_xor_sync(FULL, o.y, off);
        o.z += __shfl_xor_sync(FULL, o.z, off);
        o.w += __shfl_xor_sync(FULL, o.w, off);
    }

    if (sub == 0) {
        float4 r = make_float4(o.x + ci.x, o.y + ci.y, o.z + ci.z, o.w + ci.w);
        ((float4*)(out + (long long)gwarp * DD))[quad] = r;
    }
}

extern "C" void kernel_launch(void* const* d_in, const int* in_sizes, int n_in,
                              void* d_out, int out_size) {
    // Select inputs by element count (robust to ordering):
    const float* cur_user = nullptr;
    const float* sim_user = nullptr;
    const float* cur_item = nullptr;
    const int*   mask     = nullptr;
    for (int i = 0; i < n_in; i++) {
        switch (in_sizes[i]) {
            case 16384:     cur_user = (const float*)d_in[i]; break;
            case 163840000: sim_user = (const float*)d_in[i]; break;
            case 3276800:   cur_item = (const float*)d_in[i]; break;
            case 5120000:   mask     = (const int*)d_in[i];   break;
        }
    }
    float* out = (float*)d_out;

    int total_warps = BB * SS;                 // 102400 tiles, one warp each
    int blocks = total_warps / 4;              // 25600 blocks of 4 warps
    DIB_attn_kernel<<<blocks, 128>>>(cur_user, sim_user, cur_item, mask, out);
}